// round 4
// baseline (speedup 1.0000x reference)
#include <cuda_runtime.h>
#include <math.h>

// Input order (metadata.txt == setup_inputs dict order):
// 0 poi_idx(i32 B*N) 1 hour_of_week(i32 B*N) 2 lat 3 lon 4 t_min (f32 B*N)
// 5 region_centroids(R*2) 6 poi_emb((N_POIS+1)*D) 7 time_emb(169*D)
// 8 E_t(64) 9 E_d(64) 10 E_d_match(64) 11 region_emb(R*D) 12 Wq 13 Wk 14 Wv (D*D)
// output: f32 (B, R) = (1024, 1000)

#define BB 1024
#define NN 50
#define RR 1000
#define DD 128
#define DEG2RADF 0.017453292519943295f
#define INV_SQRT_D 0.08838834764831845f   // 1/sqrt(128)

typedef unsigned long long u64;

// scratch: S = attn @ V, layout [b][n][d]
__device__ float g_S[BB * NN * DD];

__device__ __forceinline__ u64 pk2(float lo, float hi) {
    u64 r; asm("mov.b64 %0, {%1, %2};" : "=l"(r) : "f"(lo), "f"(hi)); return r;
}
__device__ __forceinline__ void upk2(u64 v, float& lo, float& hi) {
    asm("mov.b64 {%0, %1}, %2;" : "=f"(lo), "=f"(hi) : "l"(v));
}
__device__ __forceinline__ u64 ffma2(u64 a, u64 b, u64 c) {
    u64 d; asm("fma.rn.f32x2 %0, %1, %2, %3;" : "=l"(d) : "l"(a), "l"(b), "l"(c)); return d;
}

__device__ __forceinline__ float interp64(const float* t, float x) {
    x = fminf(fmaxf(x, 0.0f), 62.999996f);
    int k = (int)x;
    float f = x - (float)k;
    return t[k] + f * (t[k + 1] - t[k]);
}

// dlat/dlon in radians, cc = cos(lat1)*cos(lat2)
__device__ __forceinline__ float hav_km(float dlatr, float dlonr, float cc) {
    float s1 = __sinf(0.5f * dlatr);
    float s2 = __sinf(0.5f * dlonr);
    float a = s1 * s1 + cc * s2 * s2;
    a = fminf(fmaxf(a, 0.0f), 1.0f);
    return 12742.0f * asinf(sqrtf(a));
}

// ---------------- Kernel 1: per-batch x, QKV, attention, S ----------------

struct S1 {
    float xT[128][52];   // x transposed [d][n], pair-contiguous over n
    float QV[50][134];   // Q[n][j]; reused as Vt[128][52] after scores
    float Kk[50][134];   // K[n][j]
    float P[50][52];     // scores -> attn [n][m]
    float Et[64];
    float Ed[64];
    float tmin_s[50];
    float latr[50];
    float lonr[50];
    float coslat[50];
    float validf[50];
    int   psafe[50];
    int   hsafe[50];
};

// thread tile: 2 output columns (j0, j0+1), up to 7 row-pairs starting at n0
__device__ __forceinline__ void qkv_gemm(const float (*xT)[52], const float* __restrict__ W,
                                         int j0, int n0, u64 a0[7], u64 a1[7]) {
#pragma unroll
    for (int k = 0; k < 7; k++) { a0[k] = 0ull; a1[k] = 0ull; }
    const float4* w0 = (const float4*)(W + j0 * 128);
    const float4* w1 = (const float4*)(W + (j0 + 1) * 128);
#pragma unroll 4
    for (int d4 = 0; d4 < 32; d4++) {
        float4 wa = __ldg(&w0[d4]);
        float4 wb = __ldg(&w1[d4]);
        float wav[4] = {wa.x, wa.y, wa.z, wa.w};
        float wbv[4] = {wb.x, wb.y, wb.z, wb.w};
#pragma unroll
        for (int dd = 0; dd < 4; dd++) {
            int d = 4 * d4 + dd;
            u64 p0 = pk2(wav[dd], wav[dd]);
            u64 p1 = pk2(wbv[dd], wbv[dd]);
#pragma unroll
            for (int k = 0; k < 7; k++) {
                u64 x2 = *(const u64*)&xT[d][n0 + 2 * k];
                a0[k] = ffma2(x2, p0, a0[k]);
                a1[k] = ffma2(x2, p1, a1[k]);
            }
        }
    }
}

__global__ void __launch_bounds__(256, 2)
stan_k1(const int* __restrict__ poi_idx, const int* __restrict__ hour,
        const float* __restrict__ lat, const float* __restrict__ lon,
        const float* __restrict__ tmin,
        const float* __restrict__ poi_emb, const float* __restrict__ time_emb,
        const float* __restrict__ E_t, const float* __restrict__ E_d,
        const float* __restrict__ Wq, const float* __restrict__ Wk,
        const float* __restrict__ Wv) {
    extern __shared__ char smraw[];
    S1* sm = (S1*)smraw;
    const int b = blockIdx.x;
    const int t = threadIdx.x;

    // per-n setup
    if (t < 50) {
        int pi = poi_idx[b * 50 + t];
        bool pad = pi < 0;
        sm->psafe[t] = pad ? 50000 : pi;
        sm->hsafe[t] = pad ? 0 : hour[b * 50 + t];
        sm->validf[t] = pad ? 0.0f : 1.0f;
        float la = lat[b * 50 + t] * DEG2RADF;
        float lo = lon[b * 50 + t] * DEG2RADF;
        sm->latr[t] = la; sm->lonr[t] = lo;
        sm->coslat[t] = cosf(la);
        sm->tmin_s[t] = tmin[b * 50 + t];
    }
    if (t >= 64 && t < 128) { sm->Et[t - 64] = E_t[t - 64]; sm->Ed[t - 64] = E_d[t - 64]; }
    __syncthreads();

    // gather x (transposed)
    for (int idx = t; idx < 50 * 128; idx += 256) {
        int n = idx >> 7, d = idx & 127;
        float v = poi_emb[sm->psafe[n] * 128 + d] + time_emb[sm->hsafe[n] * 128 + d];
        sm->xT[d][n] = v;
    }
    __syncthreads();

    const int jp = t & 63;          // 64 column-pairs
    const int qtr = t >> 6;         // 4 row-quarters
    const int j0 = 2 * jp;
    const int n0tab[4] = {0, 14, 26, 38};
    const int cnttab[4] = {7, 6, 6, 6};
    const int n0 = n0tab[qtr];
    const int cnt = cnttab[qtr];

    // Q and K passes
    {
        u64 a0[7], a1[7];
        qkv_gemm(sm->xT, Wq, j0, n0, a0, a1);
#pragma unroll
        for (int k = 0; k < 7; k++) {
            if (k < cnt) {
                float l0, h0, l1, h1; upk2(a0[k], l0, h0); upk2(a1[k], l1, h1);
                int n = n0 + 2 * k;
                *(float2*)&sm->QV[n][j0]     = make_float2(l0, l1);
                *(float2*)&sm->QV[n + 1][j0] = make_float2(h0, h1);
            }
        }
        qkv_gemm(sm->xT, Wk, j0, n0, a0, a1);
#pragma unroll
        for (int k = 0; k < 7; k++) {
            if (k < cnt) {
                float l0, h0, l1, h1; upk2(a0[k], l0, h0); upk2(a1[k], l1, h1);
                int n = n0 + 2 * k;
                *(float2*)&sm->Kk[n][j0]     = make_float2(l0, l1);
                *(float2*)&sm->Kk[n + 1][j0] = make_float2(h0, h1);
            }
        }
    }
    __syncthreads();

    // scores + bias + mask
    for (int p = t; p < 2500; p += 256) {
        int n = p / 50, m = p - n * 50;
        u64 acc = 0ull;
#pragma unroll
        for (int i = 0; i < 64; i++) {
            acc = ffma2(*(const u64*)&sm->QV[n][2 * i],
                        *(const u64*)&sm->Kk[m][2 * i], acc);
        }
        float lo, hi; upk2(acc, lo, hi);
        float s = (lo + hi) * INV_SQRT_D;
        float vp = sm->validf[n] * sm->validf[m];
        float dtm = fabsf(sm->tmin_s[n] - sm->tmin_s[m]) * vp;
        float dd = hav_km(sm->latr[m] - sm->latr[n], sm->lonr[m] - sm->lonr[n],
                          sm->coslat[n] * sm->coslat[m]) * vp;
        s += interp64(sm->Et, fminf(dtm, 10080.0f) * (63.0f / 10080.0f));
        s += interp64(sm->Ed, fminf(dd, 200.0f) * (63.0f / 200.0f));
        s = (sm->validf[m] != 0.0f) ? s : -1.0e30f;
        sm->P[n][m] = s;
    }
    __syncthreads();

    // V pass (overwrite QV as Vt[j][m]) + row softmax on P
    float (*Vt)[52] = reinterpret_cast<float(*)[52]>(sm->QV);
    {
        u64 a0[7], a1[7];
        qkv_gemm(sm->xT, Wv, j0, n0, a0, a1);
#pragma unroll
        for (int k = 0; k < 7; k++) {
            if (k < cnt) {
                *(u64*)&Vt[j0][n0 + 2 * k]     = a0[k];
                *(u64*)&Vt[j0 + 1][n0 + 2 * k] = a1[k];
            }
        }
    }
    if (t < 50) {
        float mx = -3.0e38f;
#pragma unroll
        for (int m = 0; m < 50; m++) mx = fmaxf(mx, sm->P[t][m]);
        if (mx <= -9.0e29f) {
            for (int m = 0; m < 50; m++) sm->P[t][m] = 0.0f;  // all-pad row -> nan_to_num
        } else {
            float sum = 0.0f;
#pragma unroll
            for (int m = 0; m < 50; m++) {
                float e = __expf(sm->P[t][m] - mx);
                sm->P[t][m] = e; sum += e;
            }
            float inv = 1.0f / sum;
#pragma unroll
            for (int m = 0; m < 50; m++) sm->P[t][m] *= inv;
        }
    }
    __syncthreads();

    // S = attn @ V   (pairs over m), write g_S[b][n][j] coalesced
    const int nrows = 2 * cnt;
    for (int nn = 0; nn < nrows; nn++) {
        int n = n0 + nn;
        u64 acc0 = 0ull, acc1 = 0ull;
#pragma unroll
        for (int i = 0; i < 25; i++) {
            u64 a2 = *(const u64*)&sm->P[n][2 * i];
            acc0 = ffma2(a2, *(const u64*)&Vt[j0][2 * i], acc0);
            acc1 = ffma2(a2, *(const u64*)&Vt[j0 + 1][2 * i], acc1);
        }
        float l0, h0, l1, h1; upk2(acc0, l0, h0); upk2(acc1, l1, h1);
        *(float2*)&g_S[(b * 50 + n) * 128 + j0] = make_float2(l0 + h0, l1 + h1);
    }
}

// ---------------- Kernel 2: m_scores GEMM + column softmax ----------------

__device__ __forceinline__ float k2_epilogue(u64 acc[25], float clatr, float clonr, float ccos,
                                             const float* Edm, const float* latr,
                                             const float* lonr, const float* coslat,
                                             const float* validf) {
    float mx = -3.0e38f;
#pragma unroll
    for (int k = 0; k < 25; k++) {
        float lo, hi; upk2(acc[k], lo, hi);
        int n = 2 * k;
        {
            float dd = hav_km(clatr - latr[n], clonr - lonr[n], ccos * coslat[n]);
            float s = lo * INV_SQRT_D + interp64(Edm, fminf(dd, 200.0f) * (63.0f / 200.0f));
            lo = (validf[n] != 0.0f) ? s : -1.0e30f;
        }
        {
            float dd = hav_km(clatr - latr[n + 1], clonr - lonr[n + 1], ccos * coslat[n + 1]);
            float s = hi * INV_SQRT_D + interp64(Edm, fminf(dd, 200.0f) * (63.0f / 200.0f));
            hi = (validf[n + 1] != 0.0f) ? s : -1.0e30f;
        }
        acc[k] = pk2(lo, hi);
        mx = fmaxf(mx, fmaxf(lo, hi));
    }
    if (mx <= -9.0e29f) return 0.0f;   // all-pad column -> nan_to_num
    float num = 0.0f, den = 0.0f;
#pragma unroll
    for (int k = 0; k < 25; k++) {
        float lo, hi; upk2(acc[k], lo, hi);
        float e0 = __expf(lo - mx); den += e0; num += e0 * lo;
        float e1 = __expf(hi - mx); den += e1; num += e1 * hi;
    }
    return num / den;
}

__global__ void __launch_bounds__(128)
stan_k2(const int* __restrict__ poi_idx, const float* __restrict__ lat,
        const float* __restrict__ lon, const float* __restrict__ cent,
        const float* __restrict__ E_dm, const float* __restrict__ Remb,
        float* __restrict__ out) {
    __shared__ float sS[128][52];   // S transposed [d][n], pair-contiguous over n
    __shared__ float latr[50], lonr[50], coslat[50], validf[50];
    __shared__ float Edm[64];
    const int b = blockIdx.y;
    const int rb = blockIdx.x;
    const int t = threadIdx.x;

    if (t < 50) {
        validf[t] = (poi_idx[b * 50 + t] < 0) ? 0.0f : 1.0f;
        float la = lat[b * 50 + t] * DEG2RADF;
        float lo = lon[b * 50 + t] * DEG2RADF;
        latr[t] = la; lonr[t] = lo; coslat[t] = cosf(la);
    }
    if (t >= 64) Edm[t - 64] = E_dm[t - 64];
    for (int idx = t; idx < 50 * 128; idx += 128) {
        int n = idx >> 7, d = idx & 127;
        sS[d][n] = g_S[b * 6400 + idx];
    }
    __syncthreads();

    const int r0 = rb * 256 + t;        // r0 <= 895 always valid
    const int r1 = r0 + 128;
    const bool ok1 = r1 < RR;

    u64 acc0[25], acc1[25];
#pragma unroll
    for (int k = 0; k < 25; k++) { acc0[k] = 0ull; acc1[k] = 0ull; }

    const float4* re0 = (const float4*)(Remb + (size_t)r0 * 128);
    const float4* re1 = (const float4*)(Remb + (size_t)(ok1 ? r1 : r0) * 128);
#pragma unroll 2
    for (int d4 = 0; d4 < 32; d4++) {
        float4 va = __ldg(&re0[d4]);
        float4 vb = __ldg(&re1[d4]);
        float av[4] = {va.x, va.y, va.z, va.w};
        float bv[4] = {vb.x, vb.y, vb.z, vb.w};
#pragma unroll
        for (int dd = 0; dd < 4; dd++) {
            int d = 4 * d4 + dd;
            u64 p0 = pk2(av[dd], av[dd]);
            u64 p1 = pk2(bv[dd], bv[dd]);
#pragma unroll
            for (int k = 0; k < 25; k++) {
                u64 s2 = *(const u64*)&sS[d][2 * k];
                acc0[k] = ffma2(s2, p0, acc0[k]);
                acc1[k] = ffma2(s2, p1, acc1[k]);
            }
        }
    }

    {
        float cl = cent[2 * r0] * DEG2RADF;
        float co = cent[2 * r0 + 1] * DEG2RADF;
        out[b * RR + r0] = k2_epilogue(acc0, cl, co, cosf(cl), Edm, latr, lonr, coslat, validf);
    }
    if (ok1) {
        float cl = cent[2 * r1] * DEG2RADF;
        float co = cent[2 * r1 + 1] * DEG2RADF;
        out[b * RR + r1] = k2_epilogue(acc1, cl, co, cosf(cl), Edm, latr, lonr, coslat, validf);
    }
}

// ---------------- launcher ----------------

extern "C" void kernel_launch(void* const* d_in, const int* in_sizes, int n_in,
                              void* d_out, int out_size) {
    const int*   poi_idx  = (const int*)d_in[0];
    const int*   hour     = (const int*)d_in[1];
    const float* lat      = (const float*)d_in[2];
    const float* lon      = (const float*)d_in[3];
    const float* tmin     = (const float*)d_in[4];
    const float* cent     = (const float*)d_in[5];
    const float* poi_emb  = (const float*)d_in[6];
    const float* time_emb = (const float*)d_in[7];
    const float* E_t      = (const float*)d_in[8];
    const float* E_d      = (const float*)d_in[9];
    const float* E_dm     = (const float*)d_in[10];
    const float* Remb     = (const float*)d_in[11];
    const float* Wq       = (const float*)d_in[12];
    const float* Wk       = (const float*)d_in[13];
    const float* Wv       = (const float*)d_in[14];
    float* out = (float*)d_out;

    cudaFuncSetAttribute(stan_k1, cudaFuncAttributeMaxDynamicSharedMemorySize,
                         (int)sizeof(S1));
    stan_k1<<<BB, 256, sizeof(S1)>>>(poi_idx, hour, lat, lon, tmin,
                                     poi_emb, time_emb, E_t, E_d, Wq, Wk, Wv);
    stan_k2<<<dim3(4, BB), 128>>>(poi_idx, lat, lon, cent, E_dm, Remb, out);
}

// round 6
// speedup vs baseline: 1.3784x; 1.3784x over previous
#include <cuda_runtime.h>
#include <math.h>

// Input order:
// 0 poi_idx(i32 B*N) 1 hour_of_week(i32 B*N) 2 lat 3 lon 4 t_min (f32 B*N)
// 5 region_centroids(R*2) 6 poi_emb((N_POIS+1)*D) 7 time_emb(169*D)
// 8 E_t(64) 9 E_d(64) 10 E_d_match(64) 11 region_emb(R*D) 12 Wq 13 Wk 14 Wv (D*D)
// output: f32 (B, R) = (1024, 1000)

#define BB 1024
#define NN 50
#define RR 1000
#define DD 128
#define DEG2RADF 0.017453292519943295f
#define INV_SQRT_D 0.08838834764831845f   // 1/sqrt(128)

typedef unsigned long long u64;

// scratch
__device__ float g_S[BB * NN * DD];       // S = attn @ V, [b][n][d]
__device__ float g_M[DD * DD];            // M[b][a] = sum_j Wq[j][a]*Wk[j][b]

__device__ __forceinline__ u64 pk2(float lo, float hi) {
    u64 r; asm("mov.b64 %0, {%1, %2};" : "=l"(r) : "f"(lo), "f"(hi)); return r;
}
__device__ __forceinline__ void upk2(u64 v, float& lo, float& hi) {
    asm("mov.b64 {%0, %1}, %2;" : "=f"(lo), "=f"(hi) : "l"(v));
}
__device__ __forceinline__ u64 ffma2(u64 a, u64 b, u64 c) {
    u64 d; asm("fma.rn.f32x2 %0, %1, %2, %3;" : "=l"(d) : "l"(a), "l"(b), "l"(c)); return d;
}

__device__ __forceinline__ float interp64(const float* t, float x) {
    x = fminf(fmaxf(x, 0.0f), 62.999996f);
    int k = (int)x;
    float f = x - (float)k;
    return t[k] + f * (t[k + 1] - t[k]);
}

// haversine with asin series (valid: result only used clipped to <=200km)
// dist = 12742*(s + s^3/6), s = sqrt(a)
__device__ __forceinline__ float hav_km(float dlatr, float dlonr, float cc) {
    float s1 = __sinf(0.5f * dlatr);
    float s2 = __sinf(0.5f * dlonr);
    float a = s1 * s1 + cc * s2 * s2;
    a = fminf(a, 1.0f);
    float w = sqrtf(a);
    return w * (12742.0f + 2123.6667f * a);
}

// ---------------- Kernel 0: M = Wq^T Wk  (stored transposed: g_M[b][a]) ----

__global__ void stan_k0(const float* __restrict__ Wq, const float* __restrict__ Wk) {
    int bcol = blockIdx.x;    // 0..127
    int a = threadIdx.x;      // 0..127
    float acc = 0.0f;
#pragma unroll 8
    for (int j = 0; j < 128; j++)
        acc += Wq[j * 128 + a] * Wk[j * 128 + bcol];
    g_M[bcol * 128 + a] = acc;
}

// ---------------- Kernel 1: x, Y=xM^T, scores, V, softmax, S --------------

struct S1 {
    float xT[128][52];   // x transposed [d][n]
    float YT[128][52];   // y transposed [j][n]; reused as Vt after scores
    float P[50][52];     // scores -> attn [n][m]
    float Et[64];
    float Ed[64];
    float tmin_s[50];
    float latr[50];
    float lonr[50];
    float coslat[50];
    float validf[50];
    int   psafe[50];
    int   hsafe[50];
};

// thread tile: 2 output columns (j0, j0+1), up to 7 row-pairs at n0; stores
// transposed into OT[j][n-pairs].
__device__ __forceinline__ void gemm_pass(const float (*xT)[52], float (*OT)[52],
                                          const float* __restrict__ W,
                                          int j0, int n0, int cnt) {
    u64 a0[7], a1[7];
#pragma unroll
    for (int k = 0; k < 7; k++) { a0[k] = 0ull; a1[k] = 0ull; }
    const float4* w0 = (const float4*)(W + j0 * 128);
    const float4* w1 = (const float4*)(W + (j0 + 1) * 128);
#pragma unroll 4
    for (int d4 = 0; d4 < 32; d4++) {
        float4 wa = __ldg(&w0[d4]);
        float4 wb = __ldg(&w1[d4]);
        float wav[4] = {wa.x, wa.y, wa.z, wa.w};
        float wbv[4] = {wb.x, wb.y, wb.z, wb.w};
#pragma unroll
        for (int dd = 0; dd < 4; dd++) {
            int d = 4 * d4 + dd;
            u64 p0 = pk2(wav[dd], wav[dd]);
            u64 p1 = pk2(wbv[dd], wbv[dd]);
#pragma unroll
            for (int k = 0; k < 7; k++) {
                u64 x2 = *(const u64*)&xT[d][n0 + 2 * k];
                a0[k] = ffma2(x2, p0, a0[k]);
                a1[k] = ffma2(x2, p1, a1[k]);
            }
        }
    }
#pragma unroll
    for (int k = 0; k < 7; k++) {
        if (k < cnt) {
            *(u64*)&OT[j0][n0 + 2 * k]     = a0[k];
            *(u64*)&OT[j0 + 1][n0 + 2 * k] = a1[k];
        }
    }
}

__global__ void __launch_bounds__(256, 3)
stan_k1(const int* __restrict__ poi_idx, const int* __restrict__ hour,
        const float* __restrict__ lat, const float* __restrict__ lon,
        const float* __restrict__ tmin,
        const float* __restrict__ poi_emb, const float* __restrict__ time_emb,
        const float* __restrict__ E_t, const float* __restrict__ E_d,
        const float* __restrict__ Wv) {
    extern __shared__ char smraw[];
    S1* sm = (S1*)smraw;
    const int b = blockIdx.x;
    const int t = threadIdx.x;

    if (t < 50) {
        int pi = poi_idx[b * 50 + t];
        bool pad = pi < 0;
        sm->psafe[t] = pad ? 50000 : pi;
        sm->hsafe[t] = pad ? 0 : hour[b * 50 + t];
        sm->validf[t] = pad ? 0.0f : 1.0f;
        float la = lat[b * 50 + t] * DEG2RADF;
        float lo = lon[b * 50 + t] * DEG2RADF;
        sm->latr[t] = la; sm->lonr[t] = lo;
        sm->coslat[t] = cosf(la);
        sm->tmin_s[t] = tmin[b * 50 + t];
    }
    if (t >= 64 && t < 128) { sm->Et[t - 64] = E_t[t - 64]; sm->Ed[t - 64] = E_d[t - 64]; }
    __syncthreads();

    // gather x (transposed)
    for (int idx = t; idx < 50 * 128; idx += 256) {
        int n = idx >> 7, d = idx & 127;
        sm->xT[d][n] = poi_emb[sm->psafe[n] * 128 + d] + time_emb[sm->hsafe[n] * 128 + d];
    }
    __syncthreads();

    const int jp = t & 63;
    const int qtr = t >> 6;
    const int j0 = 2 * jp;
    const int n0tab[4] = {0, 14, 26, 38};
    const int cnttab[4] = {7, 6, 6, 6};
    const int n0 = n0tab[qtr];
    const int cnt = cnttab[qtr];

    // Y = x M^T   (scores = Y x^T since M = Wq^T Wk)
    gemm_pass(sm->xT, sm->YT, g_M, j0, n0, cnt);
    __syncthreads();

    // scores: item = (n-pair, m); 25*50 = 1250 items
    for (int q = t; q < 1250; q += 256) {
        int np = q / 50, m = q - np * 50;
        int n = 2 * np;
        u64 acc = 0ull;
#pragma unroll 16
        for (int d = 0; d < 128; d++) {
            float xv = sm->xT[d][m];
            acc = ffma2(*(const u64*)&sm->YT[d][n], pk2(xv, xv), acc);
        }
        float lo, hi; upk2(acc, lo, hi);
        float vm = sm->validf[m];
        float ltm = sm->latr[m], lnm = sm->lonr[m], clm = sm->coslat[m], tm = sm->tmin_s[m];
#pragma unroll
        for (int u = 0; u < 2; u++) {
            int nn = n + u;
            float dotv = u ? hi : lo;
            float vp = sm->validf[nn] * vm;
            float dtm = fabsf(sm->tmin_s[nn] - tm) * vp;
            float dd = hav_km(ltm - sm->latr[nn], lnm - sm->lonr[nn],
                              sm->coslat[nn] * clm) * vp;
            float s = dotv * INV_SQRT_D
                    + interp64(sm->Et, fminf(dtm, 10080.0f) * 0.00625f)
                    + interp64(sm->Ed, fminf(dd, 200.0f) * 0.315f);
            sm->P[nn][m] = (vm != 0.0f) ? s : -1.0e30f;
        }
    }
    __syncthreads();

    // V pass (overwrites YT as Vt[j][m-pairs])
    gemm_pass(sm->xT, sm->YT, Wv, j0, n0, cnt);

    // row softmax on P
    if (t < 50) {
        float mx = -3.0e38f;
#pragma unroll
        for (int m = 0; m < 50; m++) mx = fmaxf(mx, sm->P[t][m]);
        if (mx <= -9.0e29f) {
            for (int m = 0; m < 50; m++) sm->P[t][m] = 0.0f;
        } else {
            float sum = 0.0f;
#pragma unroll
            for (int m = 0; m < 50; m++) {
                float e = __expf(sm->P[t][m] - mx);
                sm->P[t][m] = e; sum += e;
            }
            float inv = 1.0f / sum;
#pragma unroll
            for (int m = 0; m < 50; m++) sm->P[t][m] *= inv;
        }
    }
    __syncthreads();

    // S = attn @ V
    float (*Vt)[52] = sm->YT;
    const int nrows = 2 * cnt;
    for (int nn = 0; nn < nrows; nn++) {
        int n = n0 + nn;
        u64 acc0 = 0ull, acc1 = 0ull;
#pragma unroll
        for (int i = 0; i < 25; i++) {
            u64 a2 = *(const u64*)&sm->P[n][2 * i];
            acc0 = ffma2(a2, *(const u64*)&Vt[j0][2 * i], acc0);
            acc1 = ffma2(a2, *(const u64*)&Vt[j0 + 1][2 * i], acc1);
        }
        float l0, h0, l1, h1; upk2(acc0, l0, h0); upk2(acc1, l1, h1);
        *(float2*)&g_S[(b * 50 + n) * 128 + j0] = make_float2(l0 + h0, l1 + h1);
    }
}

// ---------------- Kernel 2: m_scores GEMM + online column softmax --------

struct S2 {
    float sS[128][52];      // S transposed [d][n-pairs], cols 50,51 zero
    float tileT[32][258];   // Remb tile transposed [d-local][row]
    float slat[50], slon[50], scos[50], sval[50];
    float Edm[64];
    float sred[128][8];     // h=1 partials: m0,den0,num0,m1,den1,num1
};

__device__ __forceinline__ void oupd(float s, float& mx, float& den, float& num) {
    float mn = fmaxf(mx, s);
    float c = __expf(mx - mn);
    float e = __expf(s - mn);
    den = den * c + e;
    num = num * c + e * s;
    mx = mn;
}

__global__ void __launch_bounds__(256, 2)
stan_k2(const int* __restrict__ poi_idx, const float* __restrict__ lat,
        const float* __restrict__ lon, const float* __restrict__ cent,
        const float* __restrict__ E_dm, const float* __restrict__ Remb,
        float* __restrict__ out) {
    extern __shared__ char smraw[];
    S2* sm = (S2*)smraw;
    const int b = blockIdx.y;
    const int rb = blockIdx.x;
    const int t = threadIdx.x;
    const int rp = t & 127;
    const int h = t >> 7;
    const int KLO = 13 * h;          // h=0: pairs 0..12, h=1: pairs 13..25(pair 25 dummy)
    const int rbase = rb * 256;
    const int r0 = rbase + 2 * rp;   // even; r1 = r0+1
    const bool rok = r0 < RR;

    if (t < 50) {
        sm->sval[t] = (poi_idx[b * 50 + t] < 0) ? 0.0f : 1.0f;
        float la = lat[b * 50 + t] * DEG2RADF;
        float lo = lon[b * 50 + t] * DEG2RADF;
        sm->slat[t] = la; sm->slon[t] = lo; sm->scos[t] = cosf(la);
    }
    if (t >= 64 && t < 128) sm->Edm[t - 64] = E_dm[t - 64];
    if (t < 128) { sm->sS[t][50] = 0.0f; sm->sS[t][51] = 0.0f; }
    for (int idx = t; idx < 50 * 128; idx += 256) {
        int n = idx >> 7, d = idx & 127;
        sm->sS[d][n] = g_S[b * 6400 + idx];
    }

    u64 acc0[13], acc1[13];
#pragma unroll
    for (int k = 0; k < 13; k++) { acc0[k] = 0ull; acc1[k] = 0ull; }

    for (int dc = 0; dc < 4; dc++) {
        __syncthreads();
        // stage Remb rows [rbase, rbase+256) x d [dc*32, dc*32+32) transposed
        for (int f = t; f < 2048; f += 256) {
            int row = f >> 3, fi = f & 7;
            int rr = rbase + row; if (rr > 999) rr = 999;
            float4 v = __ldg((const float4*)(Remb + (size_t)rr * 128 + dc * 32 + fi * 4));
            int d0 = fi * 4;
            sm->tileT[d0][row] = v.x; sm->tileT[d0 + 1][row] = v.y;
            sm->tileT[d0 + 2][row] = v.z; sm->tileT[d0 + 3][row] = v.w;
        }
        __syncthreads();
#pragma unroll 4
        for (int dl = 0; dl < 32; dl++) {
            int d = dc * 32 + dl;
            float w0, w1;
            upk2(*(const u64*)&sm->tileT[dl][2 * rp], w0, w1);
            u64 p0 = pk2(w0, w0);
            u64 p1 = pk2(w1, w1);
#pragma unroll
            for (int k = 0; k < 13; k++) {
                u64 s2 = *(const u64*)&sm->sS[d][2 * (KLO + k)];
                acc0[k] = ffma2(s2, p0, acc0[k]);
                acc1[k] = ffma2(s2, p1, acc1[k]);
            }
        }
    }

    // epilogue: bias + online softmax over this thread's n-chunk
    int rc = (r0 <= 998) ? r0 : 998;
    float cl0 = cent[2 * rc] * DEG2RADF,     co0 = cent[2 * rc + 1] * DEG2RADF;
    float cl1 = cent[2 * rc + 2] * DEG2RADF, co1 = cent[2 * rc + 3] * DEG2RADF;
    float cc0 = cosf(cl0), cc1 = cosf(cl1);
    float m0 = -3.0e38f, de0 = 0.0f, nu0 = 0.0f;
    float m1 = -3.0e38f, de1 = 0.0f, nu1 = 0.0f;

#pragma unroll
    for (int k = 0; k < 13; k++) {
        int n = 2 * (KLO + k);
        if (n < 50) {
            float lo, hi;
            upk2(acc0[k], lo, hi);
#pragma unroll
            for (int u = 0; u < 2; u++) {
                int nn = n + u;
                float dotv = u ? hi : lo;
                float dd = hav_km(sm->slat[nn] - cl0, sm->slon[nn] - co0,
                                  cc0 * sm->scos[nn]);
                float s = dotv * INV_SQRT_D + interp64(sm->Edm, dd * 0.315f);
                s = (sm->sval[nn] != 0.0f) ? s : -1.0e30f;
                oupd(s, m0, de0, nu0);
            }
            upk2(acc1[k], lo, hi);
#pragma unroll
            for (int u = 0; u < 2; u++) {
                int nn = n + u;
                float dotv = u ? hi : lo;
                float dd = hav_km(sm->slat[nn] - cl1, sm->slon[nn] - co1,
                                  cc1 * sm->scos[nn]);
                float s = dotv * INV_SQRT_D + interp64(sm->Edm, dd * 0.315f);
                s = (sm->sval[nn] != 0.0f) ? s : -1.0e30f;
                oupd(s, m1, de1, nu1);
            }
        }
    }

    if (h == 1) {
        sm->sred[rp][0] = m0; sm->sred[rp][1] = de0; sm->sred[rp][2] = nu0;
        sm->sred[rp][3] = m1; sm->sred[rp][4] = de1; sm->sred[rp][5] = nu1;
    }
    __syncthreads();
    if (h == 0 && rok) {
        float res[2];
        float pm[2] = {sm->sred[rp][0], sm->sred[rp][3]};
        float pd[2] = {sm->sred[rp][1], sm->sred[rp][4]};
        float pn[2] = {sm->sred[rp][2], sm->sred[rp][5]};
        float mm[2] = {m0, m1}, dd_[2] = {de0, de1}, nn_[2] = {nu0, nu1};
#pragma unroll
        for (int u = 0; u < 2; u++) {
            float M = fmaxf(mm[u], pm[u]);
            if (M <= -9.0e29f) res[u] = 0.0f;
            else {
                float ca = __expf(mm[u] - M), cb = __expf(pm[u] - M);
                res[u] = (nn_[u] * ca + pn[u] * cb) / (dd_[u] * ca + pd[u] * cb);
            }
        }
        *(float2*)&out[(size_t)b * RR + r0] = make_float2(res[0], res[1]);
    }
}

// ---------------- launcher ----------------

extern "C" void kernel_launch(void* const* d_in, const int* in_sizes, int n_in,
                              void* d_out, int out_size) {
    const int*   poi_idx  = (const int*)d_in[0];
    const int*   hour     = (const int*)d_in[1];
    const float* lat      = (const float*)d_in[2];
    const float* lon      = (const float*)d_in[3];
    const float* tmin     = (const float*)d_in[4];
    const float* cent     = (const float*)d_in[5];
    const float* poi_emb  = (const float*)d_in[6];
    const float* time_emb = (const float*)d_in[7];
    const float* E_t      = (const float*)d_in[8];
    const float* E_d      = (const float*)d_in[9];
    const float* E_dm     = (const float*)d_in[10];
    const float* Remb     = (const float*)d_in[11];
    const float* Wq       = (const float*)d_in[12];
    const float* Wk       = (const float*)d_in[13];
    const float* Wv       = (const float*)d_in[14];
    float* out = (float*)d_out;

    cudaFuncSetAttribute(stan_k1, cudaFuncAttributeMaxDynamicSharedMemorySize,
                         (int)sizeof(S1));
    cudaFuncSetAttribute(stan_k2, cudaFuncAttributeMaxDynamicSharedMemorySize,
                         (int)sizeof(S2));

    stan_k0<<<128, 128>>>(Wq, Wk);
    stan_k1<<<BB, 256, sizeof(S1)>>>(poi_idx, hour, lat, lon, tmin,
                                     poi_emb, time_emb, E_t, E_d, Wv);
    stan_k2<<<dim3(4, BB), 256, sizeof(S2)>>>(poi_idx, lat, lon, cent, E_dm, Remb, out);
}